// round 5
// baseline (speedup 1.0000x reference)
#include <cuda_runtime.h>

// TraceRNN: T=512, B=32, F=256, L=8
// out = [ final_trace : B*F*L ][ ys : T*B*F*L ]
// Fused chunked scan, features staged in shared memory.
// Block = 16 quads (8 feature cols) x 16 chunks of 32 steps.

#define TT  512
#define BB  32
#define FF  256
#define LL  8
#define BF  (BB * FF)        // 8192
#define BFL (BB * FF * LL)   // 65536
#define QQ  (BFL / 4)        // 16384 lambda-quads
#define CC  16               // chunks
#define CL  (TT / CC)        // 32 steps per chunk
#define QPB 16               // quads per block (8 feature columns)
#define NT  256

__global__ __launch_bounds__(NT, 6) void trace_fused(
    const float* __restrict__ features,   // [T,B,F]
    const int*   __restrict__ resets,     // [T,B]
    const float* __restrict__ carry,      // [B,F,L]
    const float* __restrict__ lambdas,    // [L]
    float*       __restrict__ out)        // [BFL + T*BFL]
{
    __shared__ float  sfeat[TT * 8];      // [t][fcol], 16 KB
    __shared__ float  snr[TT];            // (1 - reset[t,b]), 2 KB
    __shared__ float4 sP[CC][QPB];        // 4 KB
    __shared__ float4 sA[CC][QPB];        // 4 KB

    const int tid  = threadIdx.x;
    const int ql   = tid & (QPB - 1);     // quad within block
    const int c    = tid >> 4;            // chunk 0..15
    const int q    = blockIdx.x * QPB + ql;
    const int b    = q >> 9;              // 512 quads per batch row
    const int col0 = (blockIdx.x * QPB) >> 1;   // first feature col of block
    const int fcol = ql >> 1;             // local feature col 0..7
    const int t0   = c * CL;

    // ---- stage features: 8 cols x 512 t, coalesced float4 ----
    // idx in [0, 1024): t = idx>>1, half = idx&1 (two float4 per 32B row)
    for (int idx = tid; idx < TT * 2; idx += NT) {
        const int t = idx >> 1, h = idx & 1;
        float4 v = *(const float4*)(features + (size_t)t * BF + col0 + h * 4);
        *(float4*)(sfeat + t * 8 + h * 4) = v;
    }
    // ---- resets -> smem ----
    for (int i = tid; i < TT; i += NT)
        snr[i] = (resets[i * BB + b] != 0) ? 0.0f : 1.0f;

    const int   l0   = (q & 1) * 4;
    const float lam0 = __ldg(&lambdas[l0 + 0]);
    const float lam1 = __ldg(&lambdas[l0 + 1]);
    const float lam2 = __ldg(&lambdas[l0 + 2]);
    const float lam3 = __ldg(&lambdas[l0 + 3]);

    __syncthreads();

    // ---- Phase 1: chunk summary with zero init ----
    float s0 = 0.f, s1 = 0.f, s2 = 0.f, s3 = 0.f, pn = 1.0f;
    const float* fsl = sfeat + t0 * 8 + fcol;

#pragma unroll
    for (int i = 0; i < CL; ++i) {
        const float fv = fsl[i * 8];
        const float nr = snr[t0 + i];
        pn = fminf(pn, nr);
        s0 = fmaf(lam0 * nr, s0 - fv, fv);
        s1 = fmaf(lam1 * nr, s1 - fv, fv);
        s2 = fmaf(lam2 * nr, s2 - fv, fv);
        s3 = fmaf(lam3 * nr, s3 - fv, fv);
    }

    // A_l = lam^32 * pn  (5 squarings)
    float a0 = lam0, a1 = lam1, a2 = lam2, a3 = lam3;
#pragma unroll
    for (int s = 0; s < 5; ++s) { a0 *= a0; a1 *= a1; a2 *= a2; a3 *= a3; }

    sP[c][ql] = make_float4(s0, s1, s2, s3);
    sA[c][ql] = make_float4(a0 * pn, a1 * pn, a2 * pn, a3 * pn);
    __syncthreads();

    // ---- Phase 2: fold exact init for this chunk ----
    float4 tr = ((const float4*)carry)[q];
    for (int j = 0; j < c; ++j) {
        const float4 P = sP[j][ql];
        const float4 A = sA[j][ql];
        tr.x = fmaf(A.x, tr.x, P.x);
        tr.y = fmaf(A.y, tr.y, P.y);
        tr.z = fmaf(A.z, tr.z, P.z);
        tr.w = fmaf(A.w, tr.w, P.w);
    }

    // ---- Phase 3: re-run chunk from exact init, stream ys ----
    float* yb = out + (size_t)BFL + (size_t)t0 * BFL + (size_t)q * 4;

#pragma unroll
    for (int i = 0; i < CL; ++i) {
        const float fv = fsl[i * 8];
        const float nr = snr[t0 + i];
        tr.x = fmaf(lam0 * nr, tr.x - fv, fv);
        tr.y = fmaf(lam1 * nr, tr.y - fv, fv);
        tr.z = fmaf(lam2 * nr, tr.z - fv, fv);
        tr.w = fmaf(lam3 * nr, tr.w - fv, fv);
        __stcs((float4*)(yb + (size_t)i * BFL), tr);
    }

    if (c == CC - 1)
        ((float4*)out)[q] = tr;   // final trace
}

extern "C" void kernel_launch(void* const* d_in, const int* in_sizes, int n_in,
                              void* d_out, int out_size) {
    const float* features = (const float*)d_in[0];
    const int*   resets   = (const int*)d_in[1];
    const float* carry    = (const float*)d_in[2];
    const float* lambdas  = (const float*)d_in[3];
    float* out = (float*)d_out;

    trace_fused<<<QQ / QPB, NT>>>(features, resets, carry, lambdas, out);
}

// round 6
// speedup vs baseline: 1.0068x; 1.0068x over previous
#include <cuda_runtime.h>

// TraceRNN: T=512, B=32, F=256, L=8
// out = [ final_trace : B*F*L ][ ys : T*B*F*L ]
// Fused chunked scan. Block = 16 quads (8 feature cols) x 16 chunks of 32 steps.
// Features staged TRANSPOSED in smem -> LDS.128 covers 4 timesteps.

#define TT  512
#define BB  32
#define FF  256
#define LL  8
#define BF  (BB * FF)        // 8192
#define BFL (BB * FF * LL)   // 65536
#define QQ  (BFL / 4)        // 16384 lambda-quads
#define CC  16
#define CL  32
#define QPB 16
#define NT  256
#define FSTR 516             // padded t-stride (words): 16B-aligned, %32 == 4

__global__ __launch_bounds__(NT, 6) void trace_fused(
    const float* __restrict__ features,   // [T,B,F]
    const int*   __restrict__ resets,     // [T,B]
    const float* __restrict__ carry,      // [B,F,L]
    const float* __restrict__ lambdas,    // [L]
    float*       __restrict__ out)        // [BFL + T*BFL]
{
    __shared__ float  sfeatT[8 * FSTR];   // [fcol][t], ~16.5 KB
    __shared__ float  snr[TT];            // 2 KB
    __shared__ float4 sP[CC][QPB];        // 4 KB
    __shared__ float  spn[CC];            // reset-product per chunk

    const int tid  = threadIdx.x;
    const int ql   = tid & (QPB - 1);
    const int c    = tid >> 4;
    const int q    = blockIdx.x * QPB + ql;
    const int b    = q >> 9;
    const int col0 = (blockIdx.x * QPB) >> 1;  // first feature col of block
    const int fcol = ql >> 1;
    const int t0   = c * CL;

    // ---- stage features transposed: LDG.128 coalesced, STS conflict-free ----
    for (int idx = tid; idx < TT * 2; idx += NT) {
        const int t = idx >> 1, h = idx & 1;
        float4 v = *(const float4*)(features + t * BF + col0 + h * 4);
        sfeatT[(h * 4 + 0) * FSTR + t] = v.x;
        sfeatT[(h * 4 + 1) * FSTR + t] = v.y;
        sfeatT[(h * 4 + 2) * FSTR + t] = v.z;
        sfeatT[(h * 4 + 3) * FSTR + t] = v.w;
    }
    for (int i = tid; i < TT; i += NT)
        snr[i] = (resets[i * BB + b] != 0) ? 0.0f : 1.0f;

    const int   l0   = (q & 1) * 4;
    const float lam0 = __ldg(&lambdas[l0 + 0]);
    const float lam1 = __ldg(&lambdas[l0 + 1]);
    const float lam2 = __ldg(&lambdas[l0 + 2]);
    const float lam3 = __ldg(&lambdas[l0 + 3]);

    __syncthreads();

    const float* fbase = sfeatT + fcol * FSTR + t0;

    // ---- Phase 1: chunk summary with zero init ----
    float4 tr = make_float4(0.f, 0.f, 0.f, 0.f);
    float pn = 1.0f;

#define STEP(FV, NR)                                   \
    {   const float _f = (FV), _n = (NR);              \
        tr.x = fmaf(lam0 * _n, tr.x - _f, _f);         \
        tr.y = fmaf(lam1 * _n, tr.y - _f, _f);         \
        tr.z = fmaf(lam2 * _n, tr.z - _f, _f);         \
        tr.w = fmaf(lam3 * _n, tr.w - _f, _f);         }

#pragma unroll
    for (int g = 0; g < CL / 4; ++g) {
        const float4 fv = *(const float4*)(fbase + 4 * g);
        const float4 nr = *(const float4*)(snr + t0 + 4 * g);
        pn = fminf(pn, fminf(fminf(nr.x, nr.y), fminf(nr.z, nr.w)));
        STEP(fv.x, nr.x); STEP(fv.y, nr.y);
        STEP(fv.z, nr.z); STEP(fv.w, nr.w);
    }

    sP[c][ql] = tr;
    if (ql == 0) spn[c] = pn;

    // lam^32 (5 squarings) while waiting
    float a0 = lam0, a1 = lam1, a2 = lam2, a3 = lam3;
#pragma unroll
    for (int s = 0; s < 5; ++s) { a0 *= a0; a1 *= a1; a2 *= a2; a3 *= a3; }

    __syncthreads();

    // ---- Phase 2: fold exact init for this chunk ----
    tr = ((const float4*)carry)[q];
    for (int j = 0; j < c; ++j) {
        const float4 P = sP[j][ql];
        const float  w = spn[j];
        tr.x = fmaf(a0 * w, tr.x, P.x);
        tr.y = fmaf(a1 * w, tr.y, P.y);
        tr.z = fmaf(a2 * w, tr.z, P.z);
        tr.w = fmaf(a3 * w, tr.w, P.w);
    }

    // ---- Phase 3: re-run chunk from exact init, stream ys ----
    float* yb = out + BFL + t0 * BFL + q * 4;

#pragma unroll
    for (int g = 0; g < CL / 4; ++g) {
        const float4 fv = *(const float4*)(fbase + 4 * g);
        const float4 nr = *(const float4*)(snr + t0 + 4 * g);
        STEP(fv.x, nr.x); __stcs((float4*)(yb + (4 * g + 0) * BFL), tr);
        STEP(fv.y, nr.y); __stcs((float4*)(yb + (4 * g + 1) * BFL), tr);
        STEP(fv.z, nr.z); __stcs((float4*)(yb + (4 * g + 2) * BFL), tr);
        STEP(fv.w, nr.w); __stcs((float4*)(yb + (4 * g + 3) * BFL), tr);
    }
#undef STEP

    if (c == CC - 1)
        ((float4*)out)[q] = tr;   // final trace
}

extern "C" void kernel_launch(void* const* d_in, const int* in_sizes, int n_in,
                              void* d_out, int out_size) {
    const float* features = (const float*)d_in[0];
    const int*   resets   = (const int*)d_in[1];
    const float* carry    = (const float*)d_in[2];
    const float* lambdas  = (const float*)d_in[3];
    float* out = (float*)d_out;

    trace_fused<<<QQ / QPB, NT>>>(features, resets, carry, lambdas, out);
}

// round 7
// speedup vs baseline: 1.0177x; 1.0108x over previous
#include <cuda_runtime.h>

// TraceRNN: T=512, B=32, F=256, L=8
// out = [ final_trace : B*F*L ][ ys : T*B*F*L ]
// Fused chunked scan (16 chunks x 32 steps), quad-lambda threads.
// R7: resets pre-transposed by a tiny kernel; one-wave residency (7 blocks/SM).

#define TT  512
#define BB  32
#define FF  256
#define LL  8
#define BF  (BB * FF)        // 8192
#define BFL (BB * FF * LL)   // 65536
#define QQ  (BFL / 4)        // 16384 lambda-quads
#define CC  16
#define CL  32
#define QPB 16
#define NT  256
#define FSTR 516             // padded t-stride (words): 16B-aligned, %32 == 4

__device__ float g_snrT[BB * TT];   // [b][t] = (reset ? 0 : 1), 64 KB

// ---- tiny pre-kernel: transpose resets to [b][t] as float ----
__global__ __launch_bounds__(256) void prep_snr(const int* __restrict__ resets)
{
    const int i = blockIdx.x * 256 + threadIdx.x;   // i = t*32 + b (coalesced read)
    const int t = i >> 5, b = i & 31;
    g_snrT[b * TT + t] = (resets[i] != 0) ? 0.0f : 1.0f;
}

__global__ __launch_bounds__(NT, 7) void trace_fused(
    const float* __restrict__ features,   // [T,B,F]
    const float* __restrict__ carry,      // [B,F,L]
    const float* __restrict__ lambdas,    // [L]
    float*       __restrict__ out)        // [BFL + T*BFL]
{
    __shared__ float  sfeatT[8 * FSTR];   // [fcol][t], ~16.5 KB
    __shared__ float  snr[TT];            // 2 KB
    __shared__ float4 sP[CC][QPB];        // 4 KB
    __shared__ float  spn[CC];

    const int tid  = threadIdx.x;
    const int ql   = tid & (QPB - 1);
    const int c    = tid >> 4;
    const int q    = blockIdx.x * QPB + ql;
    const int b    = q >> 9;
    const int col0 = (blockIdx.x * QPB) >> 1;  // first feature col of block
    const int fcol = ql >> 1;
    const int t0   = c * CL;

    // ---- stage features transposed: LDG.128 coalesced ----
    for (int idx = tid; idx < TT * 2; idx += NT) {
        const int t = idx >> 1, h = idx & 1;
        float4 v = *(const float4*)(features + t * BF + col0 + h * 4);
        sfeatT[(h * 4 + 0) * FSTR + t] = v.x;
        sfeatT[(h * 4 + 1) * FSTR + t] = v.y;
        sfeatT[(h * 4 + 2) * FSTR + t] = v.z;
        sfeatT[(h * 4 + 3) * FSTR + t] = v.w;
    }
    // ---- resets: contiguous load from pre-transposed table ----
    for (int i = tid; i < TT; i += NT)
        snr[i] = g_snrT[b * TT + i];

    const int   l0   = (q & 1) * 4;
    const float lam0 = __ldg(&lambdas[l0 + 0]);
    const float lam1 = __ldg(&lambdas[l0 + 1]);
    const float lam2 = __ldg(&lambdas[l0 + 2]);
    const float lam3 = __ldg(&lambdas[l0 + 3]);

    __syncthreads();

    const float* fbase = sfeatT + fcol * FSTR + t0;

    // ---- Phase 1: chunk summary with zero init ----
    float4 tr = make_float4(0.f, 0.f, 0.f, 0.f);
    float pn = 1.0f;

#define STEP(FV, NR)                                   \
    {   const float _f = (FV), _n = (NR);              \
        tr.x = fmaf(lam0 * _n, tr.x - _f, _f);         \
        tr.y = fmaf(lam1 * _n, tr.y - _f, _f);         \
        tr.z = fmaf(lam2 * _n, tr.z - _f, _f);         \
        tr.w = fmaf(lam3 * _n, tr.w - _f, _f);         }

#pragma unroll
    for (int g = 0; g < CL / 4; ++g) {
        const float4 fv = *(const float4*)(fbase + 4 * g);
        const float4 nr = *(const float4*)(snr + t0 + 4 * g);
        pn = fminf(pn, fminf(fminf(nr.x, nr.y), fminf(nr.z, nr.w)));
        STEP(fv.x, nr.x); STEP(fv.y, nr.y);
        STEP(fv.z, nr.z); STEP(fv.w, nr.w);
    }

    sP[c][ql] = tr;
    if (ql == 0) spn[c] = pn;
    __syncthreads();

    // ---- Phase 2: fold exact init for this chunk ----
    // lam^32 via 5 squarings (recomputed here to keep register count low)
    float a0 = lam0, a1 = lam1, a2 = lam2, a3 = lam3;
#pragma unroll
    for (int s = 0; s < 5; ++s) { a0 *= a0; a1 *= a1; a2 *= a2; a3 *= a3; }

    tr = ((const float4*)carry)[q];
    for (int j = 0; j < c; ++j) {
        const float4 P = sP[j][ql];
        const float  w = spn[j];
        tr.x = fmaf(a0 * w, tr.x, P.x);
        tr.y = fmaf(a1 * w, tr.y, P.y);
        tr.z = fmaf(a2 * w, tr.z, P.z);
        tr.w = fmaf(a3 * w, tr.w, P.w);
    }

    // ---- Phase 3: re-run chunk from exact init, stream ys ----
    float* yb = out + BFL + t0 * BFL + q * 4;

#pragma unroll
    for (int g = 0; g < CL / 4; ++g) {
        const float4 fv = *(const float4*)(fbase + 4 * g);
        const float4 nr = *(const float4*)(snr + t0 + 4 * g);
        STEP(fv.x, nr.x); __stcs((float4*)(yb + (4 * g + 0) * BFL), tr);
        STEP(fv.y, nr.y); __stcs((float4*)(yb + (4 * g + 1) * BFL), tr);
        STEP(fv.z, nr.z); __stcs((float4*)(yb + (4 * g + 2) * BFL), tr);
        STEP(fv.w, nr.w); __stcs((float4*)(yb + (4 * g + 3) * BFL), tr);
    }
#undef STEP

    if (c == CC - 1)
        ((float4*)out)[q] = tr;   // final trace
}

extern "C" void kernel_launch(void* const* d_in, const int* in_sizes, int n_in,
                              void* d_out, int out_size) {
    const float* features = (const float*)d_in[0];
    const int*   resets   = (const int*)d_in[1];
    const float* carry    = (const float*)d_in[2];
    const float* lambdas  = (const float*)d_in[3];
    float* out = (float*)d_out;

    prep_snr<<<(TT * BB) / 256, 256>>>(resets);
    trace_fused<<<QQ / QPB, NT>>>(features, carry, lambdas, out);
}

// round 9
// speedup vs baseline: 1.0683x; 1.0496x over previous
#include <cuda_runtime.h>

// TraceRNN: T=512, B=32, F=256, L=8
// out = [ final_trace : B*F*L ][ ys : T*B*F*L ]
// Fused chunked scan (16 chunks x 32 steps), quad-lambda threads, ONE kernel.
// R9: R8 with staging-loop fix (4 iterations, full t range 0..511).

#define TT  512
#define BB  32
#define FF  256
#define LL  8
#define BF  (BB * FF)        // 8192
#define BFL (BB * FF * LL)   // 65536
#define QQ  (BFL / 4)        // 16384 lambda-quads
#define CC  16
#define CL  32
#define QPB 16
#define NT  256
#define FSTR 516             // padded t-stride (words): 16B-aligned, %32 == 4

__global__ __launch_bounds__(NT, 7) void trace_fused(
    const float* __restrict__ features,   // [T,B,F]
    const int*   __restrict__ resets,     // [T,B]
    const float* __restrict__ carry,      // [B,F,L]
    const float* __restrict__ lambdas,    // [L]
    float*       __restrict__ out)        // [BFL + T*BFL]
{
    __shared__ float  sfeatT[8 * FSTR];   // [fcol][t], ~16.5 KB
    __shared__ float  snr[TT];            // 2 KB
    __shared__ float4 sP[CC][QPB];        // 4 KB
    __shared__ float  spn[CC];

    const int tid  = threadIdx.x;
    const int lane = tid & 31;
    const int warp = tid >> 5;
    const int ql   = tid & (QPB - 1);
    const int c    = tid >> 4;
    const int q    = blockIdx.x * QPB + ql;
    const int b    = q >> 9;
    const int col0 = (blockIdx.x * QPB) >> 1;  // first feature col of block
    const int fcol = ql >> 1;
    const int t0   = c * CL;

    // ---- resets -> snr via contiguous broadcast loads ----
    // Group g covers ints [g*128, g*128+128) = timesteps 4g..4g+3, all b.
    // Value (t=4g+j, b) sits at int g*128 + j*32 + b -> lane j*8+(b>>2), comp b&3.
    {
        const int4* rbase = (const int4*)resets;
        const int   sel   = b >> 2;
        const int   cmp   = b & 3;
#pragma unroll 4
        for (int k = 0; k < 16; ++k) {
            const int g = warp * 16 + k;
            const int4 v = __ldg(&rbase[g * 32 + lane]);
            if ((lane & 7) == sel) {
                const int rv = (cmp & 2) ? ((cmp & 1) ? v.w : v.z)
                                         : ((cmp & 1) ? v.y : v.x);
                snr[4 * g + (lane >> 3)] = rv ? 0.0f : 1.0f;
            }
        }
    }

    // ---- stage features transposed: LDG.128 coalesced (1024 float4s) ----
#pragma unroll
    for (int it = 0; it < 4; ++it) {
        const int idx = it * NT + tid;            // 0..1023
        const int t = idx >> 1, h = idx & 1;
        float4 v = *(const float4*)(features + t * BF + col0 + h * 4);
        sfeatT[(h * 4 + 0) * FSTR + t] = v.x;
        sfeatT[(h * 4 + 1) * FSTR + t] = v.y;
        sfeatT[(h * 4 + 2) * FSTR + t] = v.z;
        sfeatT[(h * 4 + 3) * FSTR + t] = v.w;
    }

    const int   l0   = (q & 1) * 4;
    const float lam0 = __ldg(&lambdas[l0 + 0]);
    const float lam1 = __ldg(&lambdas[l0 + 1]);
    const float lam2 = __ldg(&lambdas[l0 + 2]);
    const float lam3 = __ldg(&lambdas[l0 + 3]);

    __syncthreads();

    const float* fbase = sfeatT + fcol * FSTR + t0;

    // ---- Phase 1: chunk summary with zero init ----
    float4 tr = make_float4(0.f, 0.f, 0.f, 0.f);
    float pn = 1.0f;

#define STEP(FV, NR)                                   \
    {   const float _f = (FV), _n = (NR);              \
        tr.x = fmaf(lam0 * _n, tr.x - _f, _f);         \
        tr.y = fmaf(lam1 * _n, tr.y - _f, _f);         \
        tr.z = fmaf(lam2 * _n, tr.z - _f, _f);         \
        tr.w = fmaf(lam3 * _n, tr.w - _f, _f);         }

#pragma unroll
    for (int g = 0; g < CL / 4; ++g) {
        const float4 fv = *(const float4*)(fbase + 4 * g);
        const float4 nr = *(const float4*)(snr + t0 + 4 * g);
        pn = fminf(pn, fminf(fminf(nr.x, nr.y), fminf(nr.z, nr.w)));
        STEP(fv.x, nr.x); STEP(fv.y, nr.y);
        STEP(fv.z, nr.z); STEP(fv.w, nr.w);
    }

    sP[c][ql] = tr;
    if (ql == 0) spn[c] = pn;
    __syncthreads();

    // ---- Phase 2: fold exact init for this chunk ----
    float a0 = lam0, a1 = lam1, a2 = lam2, a3 = lam3;
#pragma unroll
    for (int s = 0; s < 5; ++s) { a0 *= a0; a1 *= a1; a2 *= a2; a3 *= a3; }

    tr = ((const float4*)carry)[q];
    for (int j = 0; j < c; ++j) {
        const float4 P = sP[j][ql];
        const float  w = spn[j];
        tr.x = fmaf(a0 * w, tr.x, P.x);
        tr.y = fmaf(a1 * w, tr.y, P.y);
        tr.z = fmaf(a2 * w, tr.z, P.z);
        tr.w = fmaf(a3 * w, tr.w, P.w);
    }

    // ---- Phase 3: re-run chunk from exact init, stream ys ----
    float* yb = out + BFL + t0 * BFL + q * 4;

#pragma unroll
    for (int g = 0; g < CL / 4; ++g) {
        const float4 fv = *(const float4*)(fbase + 4 * g);
        const float4 nr = *(const float4*)(snr + t0 + 4 * g);
        STEP(fv.x, nr.x); __stcs((float4*)(yb + (4 * g + 0) * BFL), tr);
        STEP(fv.y, nr.y); __stcs((float4*)(yb + (4 * g + 1) * BFL), tr);
        STEP(fv.z, nr.z); __stcs((float4*)(yb + (4 * g + 2) * BFL), tr);
        STEP(fv.w, nr.w); __stcs((float4*)(yb + (4 * g + 3) * BFL), tr);
    }
#undef STEP

    if (c == CC - 1)
        ((float4*)out)[q] = tr;   // final trace
}

extern "C" void kernel_launch(void* const* d_in, const int* in_sizes, int n_in,
                              void* d_out, int out_size) {
    const float* features = (const float*)d_in[0];
    const int*   resets   = (const int*)d_in[1];
    const float* carry    = (const float*)d_in[2];
    const float* lambdas  = (const float*)d_in[3];
    float* out = (float*)d_out;

    trace_fused<<<QQ / QPB, NT>>>(features, resets, carry, lambdas, out);
}

// round 10
// speedup vs baseline: 1.0760x; 1.0073x over previous
#include <cuda_runtime.h>

// TraceRNN: T=512, B=32, F=256, L=8
// out = [ final_trace : B*F*L ][ ys : T*B*F*L ]
// Fused chunked scan (16 chunks x 32 steps), quad-lambda threads, ONE kernel.
// R10: blocks 0..15 transpose resets -> g_snrT; all blocks spin on g_flag
//      (single-wave residency guarantees producers are co-scheduled).

#define TT  512
#define BB  32
#define FF  256
#define LL  8
#define BF  (BB * FF)        // 8192
#define BFL (BB * FF * LL)   // 65536
#define QQ  (BFL / 4)        // 16384 lambda-quads
#define CC  16
#define CL  32
#define QPB 16
#define NT  256
#define FSTR 516             // padded t-stride (words)
#define NPROD 16             // producer blocks

__device__ float g_snrT[BB * TT];   // [b][t] = reset ? 0 : 1
__device__ int   g_flag;            // monotonic producer counter

__global__ __launch_bounds__(NT, 7) void trace_fused(
    const float* __restrict__ features,   // [T,B,F]
    const int*   __restrict__ resets,     // [T,B]
    const float* __restrict__ carry,      // [B,F,L]
    const float* __restrict__ lambdas,    // [L]
    float*       __restrict__ out)        // [BFL + T*BFL]
{
    __shared__ float  sfeatT[8 * FSTR];   // [fcol][t], ~16.5 KB
    __shared__ float  snr[TT];            // 2 KB
    __shared__ float4 sP[CC][QPB];        // 4 KB
    __shared__ float  spn[CC];

    const int tid  = threadIdx.x;
    const int ql   = tid & (QPB - 1);
    const int c    = tid >> 4;
    const int q    = blockIdx.x * QPB + ql;
    const int b    = q >> 9;
    const int col0 = (blockIdx.x * QPB) >> 1;  // first feature col of block
    const int fcol = ql >> 1;
    const int t0   = c * CL;

    // ---- stage features transposed: LDG.128 coalesced (issue first) ----
#pragma unroll
    for (int it = 0; it < 4; ++it) {
        const int idx = it * NT + tid;            // 0..1023
        const int t = idx >> 1, h = idx & 1;
        float4 v = *(const float4*)(features + t * BF + col0 + h * 4);
        sfeatT[(h * 4 + 0) * FSTR + t] = v.x;
        sfeatT[(h * 4 + 1) * FSTR + t] = v.y;
        sfeatT[(h * 4 + 2) * FSTR + t] = v.z;
        sfeatT[(h * 4 + 3) * FSTR + t] = v.w;
    }

    // ---- producer blocks: transpose a 32-t slice of resets -> g_snrT ----
    if (blockIdx.x < NPROD) {
        const int tbase = blockIdx.x * 32;
        // idx = (t_local<<5) | b  -> coalesced reads of resets
#pragma unroll
        for (int it = 0; it < 4; ++it) {
            const int idx = it * NT + tid;        // 0..1023
            const int tl = idx >> 5, bb = idx & 31;
            g_snrT[bb * TT + tbase + tl] =
                (resets[(tbase + tl) * BB + bb] != 0) ? 0.0f : 1.0f;
        }
        __threadfence();
        __syncthreads();                           // all writes done before count
        if (tid == 0) atomicAdd(&g_flag, 1);
    }

    const int   l0   = (q & 1) * 4;
    const float lam0 = __ldg(&lambdas[l0 + 0]);
    const float lam1 = __ldg(&lambdas[l0 + 1]);
    const float lam2 = __ldg(&lambdas[l0 + 2]);
    const float lam3 = __ldg(&lambdas[l0 + 3]);

    // ---- wait until all producer slices are published (first call only) ----
    if (tid == 0) {
        while (*(volatile int*)&g_flag < NPROD) { }
        __threadfence();
    }
    __syncthreads();

    // ---- snr: contiguous load from transposed table ----
#pragma unroll
    for (int it = 0; it < 2; ++it)
        snr[it * NT + tid] = g_snrT[b * TT + it * NT + tid];

    __syncthreads();

    const float* fbase = sfeatT + fcol * FSTR + t0;

    // ---- Phase 1: chunk summary with zero init ----
    float4 tr = make_float4(0.f, 0.f, 0.f, 0.f);
    float pn = 1.0f;

#define STEP(FV, NR)                                   \
    {   const float _f = (FV), _n = (NR);              \
        tr.x = fmaf(lam0 * _n, tr.x - _f, _f);         \
        tr.y = fmaf(lam1 * _n, tr.y - _f, _f);         \
        tr.z = fmaf(lam2 * _n, tr.z - _f, _f);         \
        tr.w = fmaf(lam3 * _n, tr.w - _f, _f);         }

#pragma unroll
    for (int g = 0; g < CL / 4; ++g) {
        const float4 fv = *(const float4*)(fbase + 4 * g);
        const float4 nr = *(const float4*)(snr + t0 + 4 * g);
        pn = fminf(pn, fminf(fminf(nr.x, nr.y), fminf(nr.z, nr.w)));
        STEP(fv.x, nr.x); STEP(fv.y, nr.y);
        STEP(fv.z, nr.z); STEP(fv.w, nr.w);
    }

    sP[c][ql] = tr;
    if (ql == 0) spn[c] = pn;
    __syncthreads();

    // ---- Phase 2: fold exact init for this chunk ----
    float a0 = lam0, a1 = lam1, a2 = lam2, a3 = lam3;
#pragma unroll
    for (int s = 0; s < 5; ++s) { a0 *= a0; a1 *= a1; a2 *= a2; a3 *= a3; }

    tr = ((const float4*)carry)[q];
    for (int j = 0; j < c; ++j) {
        const float4 P = sP[j][ql];
        const float  w = spn[j];
        tr.x = fmaf(a0 * w, tr.x, P.x);
        tr.y = fmaf(a1 * w, tr.y, P.y);
        tr.z = fmaf(a2 * w, tr.z, P.z);
        tr.w = fmaf(a3 * w, tr.w, P.w);
    }

    // ---- Phase 3: re-run chunk from exact init, stream ys ----
    float* yb = out + BFL + t0 * BFL + q * 4;

#pragma unroll
    for (int g = 0; g < CL / 4; ++g) {
        const float4 fv = *(const float4*)(fbase + 4 * g);
        const float4 nr = *(const float4*)(snr + t0 + 4 * g);
        STEP(fv.x, nr.x); __stcs((float4*)(yb + (4 * g + 0) * BFL), tr);
        STEP(fv.y, nr.y); __stcs((float4*)(yb + (4 * g + 1) * BFL), tr);
        STEP(fv.z, nr.z); __stcs((float4*)(yb + (4 * g + 2) * BFL), tr);
        STEP(fv.w, nr.w); __stcs((float4*)(yb + (4 * g + 3) * BFL), tr);
    }
#undef STEP

    if (c == CC - 1)
        ((float4*)out)[q] = tr;   // final trace
}

extern "C" void kernel_launch(void* const* d_in, const int* in_sizes, int n_in,
                              void* d_out, int out_size) {
    const float* features = (const float*)d_in[0];
    const int*   resets   = (const int*)d_in[1];
    const float* carry    = (const float*)d_in[2];
    const float* lambdas  = (const float*)d_in[3];
    float* out = (float*)d_out;

    trace_fused<<<QQ / QPB, NT>>>(features, resets, carry, lambdas, out);
}